// round 2
// baseline (speedup 1.0000x reference)
#include <cuda_runtime.h>

#define N_NODES 50000
#define N_EDGES 800000
#define DCH 64
#define NEG_SLOPE 0.2f
#define LN_EPS 1e-5f

// ---------------- scratch (no allocs allowed) ----------------
__device__ float g_xl[N_NODES * DCH];      // xl = x@Wl + bl
__device__ float g_xr[N_NODES * DCH];      // xr = x@Wr + br
__device__ float g_p[N_EDGES * 4];         // exp(logit) per edge/head
__device__ float g_denom[N_NODES * 4];     // softmax denominators
__device__ float g_agg[N_NODES * DCH];     // aggregated messages

// ---------------- K0: zero scratch ----------------
__global__ void init_kernel() {
    int idx = blockIdx.x * blockDim.x + threadIdx.x;
    int stride = gridDim.x * blockDim.x;
    for (int i = idx; i < N_NODES * DCH; i += stride) g_agg[i] = 0.f;
    for (int i = idx; i < N_NODES * 4; i += stride) g_denom[i] = 0.f;
}

// ---------------- K1: fused dual GEMM ----------------
// Block: 256 threads, 32 nodes. Each thread: 2 nodes x 4 cols, both Wl and Wr.
// smem: xT 64*36*4 = 9216 B + Wls/Wrs 2*16384 B = 41984 B (< 48 KB)
__global__ __launch_bounds__(256) void gemm_kernel(
    const float* __restrict__ x,
    const float* __restrict__ Wl, const float* __restrict__ bl,
    const float* __restrict__ Wr, const float* __restrict__ br)
{
    __shared__ __align__(16) float xT[64 * 36];   // [k][node], padded stride 36
    __shared__ __align__(16) float Wls[64 * 64];  // [k][d]
    __shared__ __align__(16) float Wrs[64 * 64];

    const int tid = threadIdx.x;
    const int node0 = blockIdx.x * 32;

    for (int i = tid; i < 64 * 64; i += 256) {
        Wls[i] = Wl[i];
        Wrs[i] = Wr[i];
    }
    for (int i = tid; i < 32 * 64; i += 256) {
        int nl = i >> 6, k = i & 63;
        int n = node0 + nl;
        xT[k * 36 + nl] = (n < N_NODES) ? x[n * 64 + k] : 0.f;
    }
    __syncthreads();

    const int dq = (tid & 15) * 4;  // output col base
    const int nq = (tid >> 4) * 2;  // local node base (2 nodes)

    float accl[2][4] = {{0.f}}, accr[2][4] = {{0.f}};

#pragma unroll 8
    for (int k = 0; k < 64; k++) {
        float2 xv = *(const float2*)&xT[k * 36 + nq];
        float4 wl = *(const float4*)&Wls[k * 64 + dq];
        float4 wr = *(const float4*)&Wrs[k * 64 + dq];
        float xa[2] = {xv.x, xv.y};
        float wla[4] = {wl.x, wl.y, wl.z, wl.w};
        float wra[4] = {wr.x, wr.y, wr.z, wr.w};
#pragma unroll
        for (int i = 0; i < 2; i++)
#pragma unroll
            for (int j = 0; j < 4; j++) {
                accl[i][j] = fmaf(xa[i], wla[j], accl[i][j]);
                accr[i][j] = fmaf(xa[i], wra[j], accr[i][j]);
            }
    }

    float4 blv = *(const float4*)&bl[dq];
    float4 brv = *(const float4*)&br[dq];
    float bla[4] = {blv.x, blv.y, blv.z, blv.w};
    float bra[4] = {brv.x, brv.y, brv.z, brv.w};

#pragma unroll
    for (int i = 0; i < 2; i++) {
        int n = node0 + nq + i;
        if (n < N_NODES) {
            float4 ol, orr;
            ol.x = accl[i][0] + bla[0]; ol.y = accl[i][1] + bla[1];
            ol.z = accl[i][2] + bla[2]; ol.w = accl[i][3] + bla[3];
            orr.x = accr[i][0] + bra[0]; orr.y = accr[i][1] + bra[1];
            orr.z = accr[i][2] + bra[2]; orr.w = accr[i][3] + bra[3];
            *(float4*)&g_xl[n * 64 + dq] = ol;
            *(float4*)&g_xr[n * 64 + dq] = orr;
        }
    }
}

__device__ __forceinline__ float lrelu(float v) {
    return v > 0.f ? v : NEG_SLOPE * v;
}

// ---------------- K2: per-edge logits -> p = exp(logit), denom += p ----------------
// 256 threads/block = 16 edges (half-warp per edge). Lane handles 4 channels.
__global__ __launch_bounds__(256) void edge_logit_kernel(
    const int* __restrict__ ei, const float* __restrict__ att)
{
    const int tid = threadIdx.x;
    const int warp = tid >> 5;
    const int lane = tid & 31;
    const int half = lane >> 4;
    const int l16 = lane & 15;
    const long long e = (long long)blockIdx.x * 16 + warp * 2 + half;
    if (e >= N_EDGES) return;
    const unsigned mask = 0xFFFFu << (half << 4);

    const int src = ei[e];
    const int dst = ei[N_EDGES + e];

    float4 a = *(const float4*)&g_xl[src * 64 + l16 * 4];
    float4 b = *(const float4*)&g_xr[dst * 64 + l16 * 4];
    float4 av = __ldg(&((const float4*)att)[l16]);

    float s = lrelu(a.x + b.x) * av.x + lrelu(a.y + b.y) * av.y +
              lrelu(a.z + b.z) * av.z + lrelu(a.w + b.w) * av.w;

    // reduce over the 4 lanes of this head (channels 16h..16h+15)
    s += __shfl_xor_sync(mask, s, 1);
    s += __shfl_xor_sync(mask, s, 2);

    if ((l16 & 3) == 0) {
        int h = l16 >> 2;
        float p = __expf(s);
        g_p[e * 4 + h] = p;
        atomicAdd(&g_denom[dst * 4 + h], p);
    }
}

// ---------------- K3: alpha-weighted scatter ----------------
__global__ __launch_bounds__(256) void edge_scatter_kernel(const int* __restrict__ ei)
{
    const int tid = threadIdx.x;
    const int warp = tid >> 5;
    const int lane = tid & 31;
    const int half = lane >> 4;
    const int l16 = lane & 15;
    const long long e = (long long)blockIdx.x * 16 + warp * 2 + half;
    if (e >= N_EDGES) return;

    const int src = ei[e];
    const int dst = ei[N_EDGES + e];
    const int h = l16 >> 2;

    float p = g_p[e * 4 + h];
    float den = g_denom[dst * 4 + h];
    float alpha = __fdividef(p, den);

    float4 a = *(const float4*)&g_xl[src * 64 + l16 * 4];
    float vx = alpha * a.x, vy = alpha * a.y, vz = alpha * a.z, vw = alpha * a.w;

    float* dp = &g_agg[dst * 64 + l16 * 4];
    asm volatile("red.global.add.v4.f32 [%0], {%1,%2,%3,%4};"
                 :: "l"(dp), "f"(vx), "f"(vy), "f"(vz), "f"(vw)
                 : "memory");
}

// ---------------- K4: residual + LayerNorm + ELU ----------------
// warp per node, lane handles 2 channels
__global__ __launch_bounds__(256) void finalize_kernel(
    const float* __restrict__ x, const float* __restrict__ bias,
    const float* __restrict__ gamma, const float* __restrict__ beta,
    float* __restrict__ out)
{
    const int tid = threadIdx.x;
    const int warp = tid >> 5;
    const int lane = tid & 31;
    const int n = blockIdx.x * 8 + warp;
    if (n >= N_NODES) return;

    float2 o = ((const float2*)g_agg)[n * 32 + lane];
    float2 xv = ((const float2*)x)[n * 32 + lane];
    float2 bv = __ldg(&((const float2*)bias)[lane]);

    float a = o.x + xv.x + bv.x;
    float b = o.y + xv.y + bv.y;

    float sum = a + b;
    float sq = a * a + b * b;
#pragma unroll
    for (int off = 16; off > 0; off >>= 1) {
        sum += __shfl_xor_sync(0xffffffff, sum, off);
        sq += __shfl_xor_sync(0xffffffff, sq, off);
    }
    float mean = sum * (1.f / 64.f);
    float var = sq * (1.f / 64.f) - mean * mean;
    float inv = rsqrtf(var + LN_EPS);

    float2 gv = __ldg(&((const float2*)gamma)[lane]);
    float2 be = __ldg(&((const float2*)beta)[lane]);

    float ya = (a - mean) * inv * gv.x + be.x;
    float yb = (b - mean) * inv * gv.y + be.y;
    ya = ya > 0.f ? ya : expm1f(ya);
    yb = yb > 0.f ? yb : expm1f(yb);

    ((float2*)out)[n * 32 + lane] = make_float2(ya, yb);
}

// ---------------- launch ----------------
extern "C" void kernel_launch(void* const* d_in, const int* in_sizes, int n_in,
                              void* d_out, int out_size)
{
    const float* x     = (const float*)d_in[0];
    const int*   ei    = (const int*)d_in[1];
    const float* Wl    = (const float*)d_in[2];
    const float* bl    = (const float*)d_in[3];
    const float* Wr    = (const float*)d_in[4];
    const float* br    = (const float*)d_in[5];
    const float* att   = (const float*)d_in[6];
    const float* bias  = (const float*)d_in[7];
    const float* gamma = (const float*)d_in[8];
    const float* beta  = (const float*)d_in[9];
    float* out = (float*)d_out;

    init_kernel<<<2048, 256>>>();
    gemm_kernel<<<(N_NODES + 31) / 32, 256>>>(x, Wl, bl, Wr, br);
    edge_logit_kernel<<<(N_EDGES + 15) / 16, 256>>>(ei, att);
    edge_scatter_kernel<<<(N_EDGES + 15) / 16, 256>>>(ei);
    finalize_kernel<<<(N_NODES + 7) / 8, 256>>>(x, bias, gamma, beta, out);
}

// round 3
// speedup vs baseline: 1.3831x; 1.3831x over previous
#include <cuda_runtime.h>

#define N_NODES 50000
#define N_EDGES 800000
#define DCH 64
#define NEG_SLOPE 0.2f
#define LN_EPS 1e-5f

// ---------------- scratch (no allocs allowed) ----------------
__device__ float g_xl[N_NODES * DCH];      // xl = x@Wl + bl
__device__ float g_xr[N_NODES * DCH];      // xr = x@Wr + br
__device__ float g_denom[N_NODES * 4];     // softmax denominators
__device__ float g_agg[N_NODES * DCH];     // unnormalized aggregated messages

// ---------------- K0: zero scratch ----------------
__global__ void init_kernel() {
    int idx = blockIdx.x * blockDim.x + threadIdx.x;
    int stride = gridDim.x * blockDim.x;
    for (int i = idx; i < N_NODES * DCH; i += stride) g_agg[i] = 0.f;
    for (int i = idx; i < N_NODES * 4; i += stride) g_denom[i] = 0.f;
}

// ---------------- K1: fused dual GEMM ----------------
// Block: 256 threads, 32 nodes. Each thread: 2 nodes x 4 cols, both Wl and Wr.
__global__ __launch_bounds__(256) void gemm_kernel(
    const float* __restrict__ x,
    const float* __restrict__ Wl, const float* __restrict__ bl,
    const float* __restrict__ Wr, const float* __restrict__ br)
{
    __shared__ __align__(16) float xT[64 * 36];   // [k][node], padded stride 36
    __shared__ __align__(16) float Wls[64 * 64];  // [k][d]
    __shared__ __align__(16) float Wrs[64 * 64];

    const int tid = threadIdx.x;
    const int node0 = blockIdx.x * 32;

    for (int i = tid; i < 64 * 64; i += 256) {
        Wls[i] = Wl[i];
        Wrs[i] = Wr[i];
    }
    for (int i = tid; i < 32 * 64; i += 256) {
        int nl = i >> 6, k = i & 63;
        int n = node0 + nl;
        xT[k * 36 + nl] = (n < N_NODES) ? x[n * 64 + k] : 0.f;
    }
    __syncthreads();

    const int dq = (tid & 15) * 4;  // output col base
    const int nq = (tid >> 4) * 2;  // local node base (2 nodes)

    float accl[2][4] = {{0.f}}, accr[2][4] = {{0.f}};

#pragma unroll 8
    for (int k = 0; k < 64; k++) {
        float2 xv = *(const float2*)&xT[k * 36 + nq];
        float4 wl = *(const float4*)&Wls[k * 64 + dq];
        float4 wr = *(const float4*)&Wrs[k * 64 + dq];
        float xa[2] = {xv.x, xv.y};
        float wla[4] = {wl.x, wl.y, wl.z, wl.w};
        float wra[4] = {wr.x, wr.y, wr.z, wr.w};
#pragma unroll
        for (int i = 0; i < 2; i++)
#pragma unroll
            for (int j = 0; j < 4; j++) {
                accl[i][j] = fmaf(xa[i], wla[j], accl[i][j]);
                accr[i][j] = fmaf(xa[i], wra[j], accr[i][j]);
            }
    }

    float4 blv = *(const float4*)&bl[dq];
    float4 brv = *(const float4*)&br[dq];
    float bla[4] = {blv.x, blv.y, blv.z, blv.w};
    float bra[4] = {brv.x, brv.y, brv.z, brv.w};

#pragma unroll
    for (int i = 0; i < 2; i++) {
        int n = node0 + nq + i;
        if (n < N_NODES) {
            float4 ol, orr;
            ol.x = accl[i][0] + bla[0]; ol.y = accl[i][1] + bla[1];
            ol.z = accl[i][2] + bla[2]; ol.w = accl[i][3] + bla[3];
            orr.x = accr[i][0] + bra[0]; orr.y = accr[i][1] + bra[1];
            orr.z = accr[i][2] + bra[2]; orr.w = accr[i][3] + bra[3];
            *(float4*)&g_xl[n * 64 + dq] = ol;
            *(float4*)&g_xr[n * 64 + dq] = orr;
        }
    }
}

__device__ __forceinline__ float lrelu(float v) {
    return v > 0.f ? v : NEG_SLOPE * v;
}

// ---------------- K2: FUSED edge pass ----------------
// Per edge: logit -> p = exp(logit); scatter p*xl[src] into agg, p into denom.
// Normalization (divide by denom) happens in finalize — exact algebraic identity.
// 256 threads/block = 16 edges (half-warp per edge). Lane handles 4 channels.
// 800000 % 16 == 0 -> no bounds check.
__global__ __launch_bounds__(256) void edge_kernel(
    const int* __restrict__ ei, const float* __restrict__ att)
{
    const int tid = threadIdx.x;
    const int warp = tid >> 5;
    const int lane = tid & 31;
    const int half = lane >> 4;
    const int l16 = lane & 15;
    const int e = blockIdx.x * 16 + warp * 2 + half;

    const int src = __ldg(&ei[e]);
    const int dst = __ldg(&ei[N_EDGES + e]);

    float4 a = *(const float4*)&g_xl[src * 64 + l16 * 4];
    float4 b = *(const float4*)&g_xr[dst * 64 + l16 * 4];
    float4 av = __ldg(&((const float4*)att)[l16]);

    float s = lrelu(a.x + b.x) * av.x + lrelu(a.y + b.y) * av.y +
              lrelu(a.z + b.z) * av.z + lrelu(a.w + b.w) * av.w;

    // butterfly over the 4 lanes of this head -> every lane holds head sum
    s += __shfl_xor_sync(0xffffffffu, s, 1);
    s += __shfl_xor_sync(0xffffffffu, s, 2);

    const float p = __expf(s);

    float vx = p * a.x, vy = p * a.y, vz = p * a.z, vw = p * a.w;
    float* dp = &g_agg[dst * 64 + l16 * 4];
    asm volatile("red.global.add.v4.f32 [%0], {%1,%2,%3,%4};"
                 :: "l"(dp), "f"(vx), "f"(vy), "f"(vz), "f"(vw)
                 : "memory");

    if ((l16 & 3) == 0) {
        atomicAdd(&g_denom[dst * 4 + (l16 >> 2)], p);
    }
}

// ---------------- K3: normalize + residual + LayerNorm + ELU ----------------
// warp per node, lane handles 2 channels (both in the same head: head = lane>>3)
__global__ __launch_bounds__(256) void finalize_kernel(
    const float* __restrict__ x, const float* __restrict__ bias,
    const float* __restrict__ gamma, const float* __restrict__ beta,
    float* __restrict__ out)
{
    const int tid = threadIdx.x;
    const int warp = tid >> 5;
    const int lane = tid & 31;
    const int n = blockIdx.x * 8 + warp;

    float2 o = ((const float2*)g_agg)[n * 32 + lane];
    float den = g_denom[n * 4 + (lane >> 3)];
    float inv_den = __fdividef(1.f, den);

    float2 xv = ((const float2*)x)[n * 32 + lane];
    float2 bv = __ldg(&((const float2*)bias)[lane]);

    float a = o.x * inv_den + xv.x + bv.x;
    float b = o.y * inv_den + xv.y + bv.y;

    float sum = a + b;
    float sq = a * a + b * b;
#pragma unroll
    for (int off = 16; off > 0; off >>= 1) {
        sum += __shfl_xor_sync(0xffffffff, sum, off);
        sq += __shfl_xor_sync(0xffffffff, sq, off);
    }
    float mean = sum * (1.f / 64.f);
    float var = sq * (1.f / 64.f) - mean * mean;
    float inv = rsqrtf(var + LN_EPS);

    float2 gv = __ldg(&((const float2*)gamma)[lane]);
    float2 be = __ldg(&((const float2*)beta)[lane]);

    float ya = (a - mean) * inv * gv.x + be.x;
    float yb = (b - mean) * inv * gv.y + be.y;
    ya = ya > 0.f ? ya : expm1f(ya);
    yb = yb > 0.f ? yb : expm1f(yb);

    ((float2*)out)[n * 32 + lane] = make_float2(ya, yb);
}

// ---------------- launch ----------------
extern "C" void kernel_launch(void* const* d_in, const int* in_sizes, int n_in,
                              void* d_out, int out_size)
{
    const float* x     = (const float*)d_in[0];
    const int*   ei    = (const int*)d_in[1];
    const float* Wl    = (const float*)d_in[2];
    const float* bl    = (const float*)d_in[3];
    const float* Wr    = (const float*)d_in[4];
    const float* br    = (const float*)d_in[5];
    const float* att   = (const float*)d_in[6];
    const float* bias  = (const float*)d_in[7];
    const float* gamma = (const float*)d_in[8];
    const float* beta  = (const float*)d_in[9];
    float* out = (float*)d_out;

    init_kernel<<<1024, 256>>>();
    gemm_kernel<<<(N_NODES + 31) / 32, 256>>>(x, Wl, bl, Wr, br);
    edge_kernel<<<N_EDGES / 16, 256>>>(ei, att);
    finalize_kernel<<<N_NODES / 8, 256>>>(x, bias, gamma, beta, out);
}

// round 4
// speedup vs baseline: 1.5281x; 1.1048x over previous
#include <cuda_runtime.h>

#define N_NODES 50000
#define N_EDGES 800000
#define DCH 64
#define NEG_SLOPE 0.2f
#define LN_EPS 1e-5f

// ---------------- scratch (no allocs allowed) ----------------
__device__ float g_xl[N_NODES * DCH];      // xl = x@Wl + bl
__device__ float g_xr[N_NODES * DCH];      // xr = x@Wr + br
__device__ float g_denom[N_NODES * 4];     // softmax denominators
__device__ float g_agg[N_NODES * DCH];     // unnormalized aggregated messages

// ---------------- K1: fused dual GEMM + scratch zeroing ----------------
// Block: 256 threads, 32 nodes. Each thread: 2 nodes x 4 cols, both Wl and Wr.
// Also zeroes this tile's g_agg / g_denom rows (overlaps with smem staging).
__global__ __launch_bounds__(256) void gemm_kernel(
    const float* __restrict__ x,
    const float* __restrict__ Wl, const float* __restrict__ bl,
    const float* __restrict__ Wr, const float* __restrict__ br)
{
    __shared__ __align__(16) float xT[64 * 36];   // [k][node], padded stride 36
    __shared__ __align__(16) float Wls[64 * 64];  // [k][d]
    __shared__ __align__(16) float Wrs[64 * 64];

    const int tid = threadIdx.x;
    const int node0 = blockIdx.x * 32;

    // zero agg (32 nodes * 64 ch = 2048 floats = 512 float4) + denom (128 floats)
    {
        const float4 z4 = make_float4(0.f, 0.f, 0.f, 0.f);
#pragma unroll
        for (int i = 0; i < 2; i++) {
            int q = tid + i * 256;                 // float4 index within tile
            int n = node0 + (q >> 4);
            if (n < N_NODES)
                ((float4*)g_agg)[(size_t)node0 * 16 + q] = z4;
        }
        if (tid < 128) {
            int n = node0 + (tid >> 2);
            if (n < N_NODES) g_denom[node0 * 4 + tid] = 0.f;
        }
    }

    for (int i = tid; i < 64 * 64; i += 256) {
        Wls[i] = Wl[i];
        Wrs[i] = Wr[i];
    }
    for (int i = tid; i < 32 * 64; i += 256) {
        int nl = i >> 6, k = i & 63;
        int n = node0 + nl;
        xT[k * 36 + nl] = (n < N_NODES) ? x[n * 64 + k] : 0.f;
    }
    __syncthreads();

    const int dq = (tid & 15) * 4;  // output col base
    const int nq = (tid >> 4) * 2;  // local node base (2 nodes)

    float accl[2][4] = {{0.f}}, accr[2][4] = {{0.f}};

#pragma unroll 8
    for (int k = 0; k < 64; k++) {
        float2 xv = *(const float2*)&xT[k * 36 + nq];
        float4 wl = *(const float4*)&Wls[k * 64 + dq];
        float4 wr = *(const float4*)&Wrs[k * 64 + dq];
        float xa[2] = {xv.x, xv.y};
        float wla[4] = {wl.x, wl.y, wl.z, wl.w};
        float wra[4] = {wr.x, wr.y, wr.z, wr.w};
#pragma unroll
        for (int i = 0; i < 2; i++)
#pragma unroll
            for (int j = 0; j < 4; j++) {
                accl[i][j] = fmaf(xa[i], wla[j], accl[i][j]);
                accr[i][j] = fmaf(xa[i], wra[j], accr[i][j]);
            }
    }

    float4 blv = *(const float4*)&bl[dq];
    float4 brv = *(const float4*)&br[dq];
    float bla[4] = {blv.x, blv.y, blv.z, blv.w};
    float bra[4] = {brv.x, brv.y, brv.z, brv.w};

#pragma unroll
    for (int i = 0; i < 2; i++) {
        int n = node0 + nq + i;
        if (n < N_NODES) {
            float4 ol, orr;
            ol.x = accl[i][0] + bla[0]; ol.y = accl[i][1] + bla[1];
            ol.z = accl[i][2] + bla[2]; ol.w = accl[i][3] + bla[3];
            orr.x = accr[i][0] + bra[0]; orr.y = accr[i][1] + bra[1];
            orr.z = accr[i][2] + bra[2]; orr.w = accr[i][3] + bra[3];
            *(float4*)&g_xl[n * 64 + dq] = ol;
            *(float4*)&g_xr[n * 64 + dq] = orr;
        }
    }
}

__device__ __forceinline__ float lrelu(float v) {
    return v > 0.f ? v : NEG_SLOPE * v;
}

// ---------------- K2: FUSED edge pass, 2 edges per half-warp ----------------
// Per edge: p = exp(att . lrelu(xl[src]+xr[dst])); RED p*xl[src] into agg,
// p into denom. Division deferred to finalize (exact identity).
// Block = 256 threads = 8 warps = 16 half-warps = 32 edges. 800000 % 32 == 0.
__global__ __launch_bounds__(256) void edge_kernel(
    const int* __restrict__ ei, const float* __restrict__ att)
{
    const int tid = threadIdx.x;
    const int lane = tid & 31;
    const int half = lane >> 4;
    const int l16 = lane & 15;
    const int e0 = blockIdx.x * 32 + (tid >> 5) * 4 + half * 2;  // this half-warp: e0, e0+1

    const int src0 = __ldg(&ei[e0]);
    const int dst0 = __ldg(&ei[N_EDGES + e0]);
    const int src1 = __ldg(&ei[e0 + 1]);
    const int dst1 = __ldg(&ei[N_EDGES + e0 + 1]);

    // all four gathers in flight before any use (MLP=4)
    float4 a0 = *(const float4*)&g_xl[src0 * 64 + l16 * 4];
    float4 b0 = *(const float4*)&g_xr[dst0 * 64 + l16 * 4];
    float4 a1 = *(const float4*)&g_xl[src1 * 64 + l16 * 4];
    float4 b1 = *(const float4*)&g_xr[dst1 * 64 + l16 * 4];
    float4 av = __ldg(&((const float4*)att)[l16]);

    float s0 = lrelu(a0.x + b0.x) * av.x + lrelu(a0.y + b0.y) * av.y +
               lrelu(a0.z + b0.z) * av.z + lrelu(a0.w + b0.w) * av.w;
    float s1 = lrelu(a1.x + b1.x) * av.x + lrelu(a1.y + b1.y) * av.y +
               lrelu(a1.z + b1.z) * av.z + lrelu(a1.w + b1.w) * av.w;

    // butterfly over the 4 lanes of each head -> every lane holds its head sum
    s0 += __shfl_xor_sync(0xffffffffu, s0, 1);
    s0 += __shfl_xor_sync(0xffffffffu, s0, 2);
    s1 += __shfl_xor_sync(0xffffffffu, s1, 1);
    s1 += __shfl_xor_sync(0xffffffffu, s1, 2);

    const float p0 = __expf(s0);
    const float p1 = __expf(s1);

    float* dp0 = &g_agg[dst0 * 64 + l16 * 4];
    asm volatile("red.global.add.v4.f32 [%0], {%1,%2,%3,%4};"
                 :: "l"(dp0), "f"(p0 * a0.x), "f"(p0 * a0.y), "f"(p0 * a0.z), "f"(p0 * a0.w)
                 : "memory");
    float* dp1 = &g_agg[dst1 * 64 + l16 * 4];
    asm volatile("red.global.add.v4.f32 [%0], {%1,%2,%3,%4};"
                 :: "l"(dp1), "f"(p1 * a1.x), "f"(p1 * a1.y), "f"(p1 * a1.z), "f"(p1 * a1.w)
                 : "memory");

    if ((l16 & 3) == 0) {
        atomicAdd(&g_denom[dst0 * 4 + (l16 >> 2)], p0);
        atomicAdd(&g_denom[dst1 * 4 + (l16 >> 2)], p1);
    }
}

// ---------------- K3: normalize + residual + LayerNorm + ELU ----------------
// Warp handles 2 nodes; each of the 16 lanes handles 4 ch (float4).
// 50000 % 16 == 0 -> grid 3125, no bounds checks.
__global__ __launch_bounds__(256) void finalize_kernel(
    const float* __restrict__ x, const float* __restrict__ bias,
    const float* __restrict__ gamma, const float* __restrict__ beta,
    float* __restrict__ out)
{
    const int tid = threadIdx.x;
    const int lane = tid & 31;
    const int half = lane >> 4;
    const int l16 = lane & 15;
    const int n = blockIdx.x * 16 + (tid >> 5) * 2 + half;

    float4 o = ((const float4*)g_agg)[n * 16 + l16];
    float den = g_denom[n * 4 + (l16 >> 2)];
    float inv_den = __fdividef(1.f, den);

    float4 xv = ((const float4*)x)[n * 16 + l16];
    float4 bv = __ldg(&((const float4*)bias)[l16]);

    float c0 = fmaf(o.x, inv_den, xv.x + bv.x);
    float c1 = fmaf(o.y, inv_den, xv.y + bv.y);
    float c2 = fmaf(o.z, inv_den, xv.z + bv.z);
    float c3 = fmaf(o.w, inv_den, xv.w + bv.w);

    float sum = c0 + c1 + c2 + c3;
    float sq = c0 * c0 + c1 * c1 + c2 * c2 + c3 * c3;
#pragma unroll
    for (int off = 8; off > 0; off >>= 1) {    // stays within the 16-lane half
        sum += __shfl_xor_sync(0xffffffff, sum, off);
        sq += __shfl_xor_sync(0xffffffff, sq, off);
    }
    float mean = sum * (1.f / 64.f);
    float var = sq * (1.f / 64.f) - mean * mean;
    float inv = rsqrtf(var + LN_EPS);

    float4 gv = __ldg(&((const float4*)gamma)[l16]);
    float4 be = __ldg(&((const float4*)beta)[l16]);

    float y0 = (c0 - mean) * inv * gv.x + be.x;
    float y1 = (c1 - mean) * inv * gv.y + be.y;
    float y2 = (c2 - mean) * inv * gv.z + be.z;
    float y3 = (c3 - mean) * inv * gv.w + be.w;
    y0 = y0 > 0.f ? y0 : expm1f(y0);
    y1 = y1 > 0.f ? y1 : expm1f(y1);
    y2 = y2 > 0.f ? y2 : expm1f(y2);
    y3 = y3 > 0.f ? y3 : expm1f(y3);

    float4 r; r.x = y0; r.y = y1; r.z = y2; r.w = y3;
    ((float4*)out)[n * 16 + l16] = r;
}

// ---------------- launch ----------------
extern "C" void kernel_launch(void* const* d_in, const int* in_sizes, int n_in,
                              void* d_out, int out_size)
{
    const float* x     = (const float*)d_in[0];
    const int*   ei    = (const int*)d_in[1];
    const float* Wl    = (const float*)d_in[2];
    const float* bl    = (const float*)d_in[3];
    const float* Wr    = (const float*)d_in[4];
    const float* br    = (const float*)d_in[5];
    const float* att   = (const float*)d_in[6];
    const float* bias  = (const float*)d_in[7];
    const float* gamma = (const float*)d_in[8];
    const float* beta  = (const float*)d_in[9];
    float* out = (float*)d_out;

    gemm_kernel<<<(N_NODES + 31) / 32, 256>>>(x, Wl, bl, Wr, br);
    edge_kernel<<<N_EDGES / 32, 256>>>(ei, att);
    finalize_kernel<<<N_NODES / 16, 256>>>(x, bias, gamma, beta, out);
}

// round 6
// speedup vs baseline: 1.8333x; 1.1998x over previous
#include <cuda_runtime.h>

#define N_NODES 50000
#define N_EDGES 800000
#define DCH 64
#define NEG_SLOPE 0.2f
#define LN_EPS 1e-5f

// ---------------- scratch (no allocs allowed) ----------------
__device__ float g_xl[N_NODES * DCH];      // xl = x@Wl + bl
__device__ float g_xr[N_NODES * DCH];      // xr = x@Wr + br
__device__ float g_denom[N_NODES * 4];     // softmax denominators
__device__ float g_agg[N_NODES * DCH];     // unnormalized aggregated messages

// ---------------- K1: fused dual GEMM + scratch zeroing ----------------
// 512 threads, 128-node tile, dynamic smem (66.5 KB):
//   xT  [64][132]  (node-major columns, padded)
//   Wls [64][64], Wrs [64][64]
// Each thread: 4 nodes x 4 cols x both matrices = 32 accumulators.
#define GEMM_TILE 128
#define XT_STRIDE 132

__global__ __launch_bounds__(512, 2) void gemm_kernel(
    const float* __restrict__ x,
    const float* __restrict__ Wl, const float* __restrict__ bl,
    const float* __restrict__ Wr, const float* __restrict__ br)
{
    extern __shared__ __align__(16) float smem[];
    float* xT  = smem;                     // 64*132 = 8448 floats
    float* Wls = smem + 64 * XT_STRIDE;    // 4096 floats
    float* Wrs = Wls + 4096;               // 4096 floats

    const int tid = threadIdx.x;
    const int node0 = blockIdx.x * GEMM_TILE;

    // ---- zero this tile's g_agg / g_denom (overlaps with staging) ----
    {
        const float4 z4 = make_float4(0.f, 0.f, 0.f, 0.f);
#pragma unroll
        for (int i = 0; i < 4; i++) {
            int q = tid + i * 512;                  // float4 idx within tile (0..2047)
            int n = node0 + (q >> 4);
            if (n < N_NODES)
                ((float4*)g_agg)[(size_t)node0 * 16 + q] = z4;
        }
        int n = node0 + (tid >> 2);
        if (n < N_NODES) g_denom[node0 * 4 + tid] = 0.f;
    }

    // ---- stage W (float4, coalesced) ----
#pragma unroll
    for (int i = tid; i < 1024; i += 512) {
        ((float4*)Wls)[i] = __ldg(&((const float4*)Wl)[i]);
        ((float4*)Wrs)[i] = __ldg(&((const float4*)Wr)[i]);
    }

    // ---- stage x transposed: xT[k][node_local] ----
    for (int i4 = tid; i4 < GEMM_TILE * 16; i4 += 512) {   // 2048 float4 reads
        int nl = i4 >> 4;
        int k4 = (i4 & 15) * 4;
        int n = node0 + nl;
        float4 v = (n < N_NODES) ? ((const float4*)x)[(size_t)n * 16 + (i4 & 15)]
                                 : make_float4(0.f, 0.f, 0.f, 0.f);
        xT[(k4 + 0) * XT_STRIDE + nl] = v.x;
        xT[(k4 + 1) * XT_STRIDE + nl] = v.y;
        xT[(k4 + 2) * XT_STRIDE + nl] = v.z;
        xT[(k4 + 3) * XT_STRIDE + nl] = v.w;
    }
    __syncthreads();

    const int dq = (tid & 15) * 4;   // output col base (16 groups)
    const int nq = (tid >> 4) * 4;   // local node base  (32 groups x 4 nodes)

    float accl[4][4] = {{0.f}}, accr[4][4] = {{0.f}};

#pragma unroll 4
    for (int k = 0; k < 64; k++) {
        float4 xv = *(const float4*)&xT[k * XT_STRIDE + nq];
        float4 wl = *(const float4*)&Wls[k * 64 + dq];
        float4 wr = *(const float4*)&Wrs[k * 64 + dq];
        float xa[4] = {xv.x, xv.y, xv.z, xv.w};
        float wla[4] = {wl.x, wl.y, wl.z, wl.w};
        float wra[4] = {wr.x, wr.y, wr.z, wr.w};
#pragma unroll
        for (int i = 0; i < 4; i++)
#pragma unroll
            for (int j = 0; j < 4; j++) {
                accl[i][j] = fmaf(xa[i], wla[j], accl[i][j]);
                accr[i][j] = fmaf(xa[i], wra[j], accr[i][j]);
            }
    }

    float4 blv = *(const float4*)&bl[dq];
    float4 brv = *(const float4*)&br[dq];
    float bla[4] = {blv.x, blv.y, blv.z, blv.w};
    float bra[4] = {brv.x, brv.y, brv.z, brv.w};

#pragma unroll
    for (int i = 0; i < 4; i++) {
        int n = node0 + nq + i;
        if (n < N_NODES) {
            float4 ol, orr;
            ol.x = accl[i][0] + bla[0]; ol.y = accl[i][1] + bla[1];
            ol.z = accl[i][2] + bla[2]; ol.w = accl[i][3] + bla[3];
            orr.x = accr[i][0] + bra[0]; orr.y = accr[i][1] + bra[1];
            orr.z = accr[i][2] + bra[2]; orr.w = accr[i][3] + bra[3];
            *(float4*)&g_xl[(size_t)n * 64 + dq] = ol;
            *(float4*)&g_xr[(size_t)n * 64 + dq] = orr;
        }
    }
}

__device__ __forceinline__ float lrelu(float v) {
    return v > 0.f ? v : NEG_SLOPE * v;
}

// ---------------- K2: FUSED edge pass, 2 edges per half-warp ----------------
__global__ __launch_bounds__(256) void edge_kernel(
    const int* __restrict__ ei, const float* __restrict__ att)
{
    const int tid = threadIdx.x;
    const int lane = tid & 31;
    const int half = lane >> 4;
    const int l16 = lane & 15;
    const int e0 = blockIdx.x * 32 + (tid >> 5) * 4 + half * 2;

    const int src0 = __ldg(&ei[e0]);
    const int dst0 = __ldg(&ei[N_EDGES + e0]);
    const int src1 = __ldg(&ei[e0 + 1]);
    const int dst1 = __ldg(&ei[N_EDGES + e0 + 1]);

    float4 a0 = *(const float4*)&g_xl[src0 * 64 + l16 * 4];
    float4 b0 = *(const float4*)&g_xr[dst0 * 64 + l16 * 4];
    float4 a1 = *(const float4*)&g_xl[src1 * 64 + l16 * 4];
    float4 b1 = *(const float4*)&g_xr[dst1 * 64 + l16 * 4];
    float4 av = __ldg(&((const float4*)att)[l16]);

    float s0 = lrelu(a0.x + b0.x) * av.x + lrelu(a0.y + b0.y) * av.y +
               lrelu(a0.z + b0.z) * av.z + lrelu(a0.w + b0.w) * av.w;
    float s1 = lrelu(a1.x + b1.x) * av.x + lrelu(a1.y + b1.y) * av.y +
               lrelu(a1.z + b1.z) * av.z + lrelu(a1.w + b1.w) * av.w;

    s0 += __shfl_xor_sync(0xffffffffu, s0, 1);
    s0 += __shfl_xor_sync(0xffffffffu, s0, 2);
    s1 += __shfl_xor_sync(0xffffffffu, s1, 1);
    s1 += __shfl_xor_sync(0xffffffffu, s1, 2);

    const float p0 = __expf(s0);
    const float p1 = __expf(s1);

    float* dp0 = &g_agg[dst0 * 64 + l16 * 4];
    asm volatile("red.global.add.v4.f32 [%0], {%1,%2,%3,%4};"
                 :: "l"(dp0), "f"(p0 * a0.x), "f"(p0 * a0.y), "f"(p0 * a0.z), "f"(p0 * a0.w)
                 : "memory");
    float* dp1 = &g_agg[dst1 * 64 + l16 * 4];
    asm volatile("red.global.add.v4.f32 [%0], {%1,%2,%3,%4};"
                 :: "l"(dp1), "f"(p1 * a1.x), "f"(p1 * a1.y), "f"(p1 * a1.z), "f"(p1 * a1.w)
                 : "memory");

    if ((l16 & 3) == 0) {
        atomicAdd(&g_denom[dst0 * 4 + (l16 >> 2)], p0);
        atomicAdd(&g_denom[dst1 * 4 + (l16 >> 2)], p1);
    }
}

// ---------------- K3: normalize + residual + LayerNorm + ELU ----------------
__global__ __launch_bounds__(256) void finalize_kernel(
    const float* __restrict__ x, const float* __restrict__ bias,
    const float* __restrict__ gamma, const float* __restrict__ beta,
    float* __restrict__ out)
{
    const int tid = threadIdx.x;
    const int lane = tid & 31;
    const int half = lane >> 4;
    const int l16 = lane & 15;
    const int n = blockIdx.x * 16 + (tid >> 5) * 2 + half;

    float4 o = ((const float4*)g_agg)[n * 16 + l16];
    float den = g_denom[n * 4 + (l16 >> 2)];
    float inv_den = __fdividef(1.f, den);

    float4 xv = ((const float4*)x)[n * 16 + l16];
    float4 bv = __ldg(&((const float4*)bias)[l16]);

    float c0 = fmaf(o.x, inv_den, xv.x + bv.x);
    float c1 = fmaf(o.y, inv_den, xv.y + bv.y);
    float c2 = fmaf(o.z, inv_den, xv.z + bv.z);
    float c3 = fmaf(o.w, inv_den, xv.w + bv.w);

    float sum = c0 + c1 + c2 + c3;
    float sq = c0 * c0 + c1 * c1 + c2 * c2 + c3 * c3;
#pragma unroll
    for (int off = 8; off > 0; off >>= 1) {
        sum += __shfl_xor_sync(0xffffffff, sum, off);
        sq += __shfl_xor_sync(0xffffffff, sq, off);
    }
    float mean = sum * (1.f / 64.f);
    float var = sq * (1.f / 64.f) - mean * mean;
    float inv = rsqrtf(var + LN_EPS);

    float4 gv = __ldg(&((const float4*)gamma)[l16]);
    float4 be = __ldg(&((const float4*)beta)[l16]);

    float y0 = (c0 - mean) * inv * gv.x + be.x;
    float y1 = (c1 - mean) * inv * gv.y + be.y;
    float y2 = (c2 - mean) * inv * gv.z + be.z;
    float y3 = (c3 - mean) * inv * gv.w + be.w;
    y0 = y0 > 0.f ? y0 : expm1f(y0);
    y1 = y1 > 0.f ? y1 : expm1f(y1);
    y2 = y2 > 0.f ? y2 : expm1f(y2);
    y3 = y3 > 0.f ? y3 : expm1f(y3);

    float4 r; r.x = y0; r.y = y1; r.z = y2; r.w = y3;
    ((float4*)out)[n * 16 + l16] = r;
}

// ---------------- launch ----------------
#define GEMM_SMEM (64 * XT_STRIDE * 4 + 2 * 4096 * 4)   // 66560 B

extern "C" void kernel_launch(void* const* d_in, const int* in_sizes, int n_in,
                              void* d_out, int out_size)
{
    const float* x     = (const float*)d_in[0];
    const int*   ei    = (const int*)d_in[1];
    const float* Wl    = (const float*)d_in[2];
    const float* bl    = (const float*)d_in[3];
    const float* Wr    = (const float*)d_in[4];
    const float* br    = (const float*)d_in[5];
    const float* att   = (const float*)d_in[6];
    const float* bias  = (const float*)d_in[7];
    const float* gamma = (const float*)d_in[8];
    const float* beta  = (const float*)d_in[9];
    float* out = (float*)d_out;

    cudaFuncSetAttribute(gemm_kernel,
                         cudaFuncAttributeMaxDynamicSharedMemorySize, GEMM_SMEM);

    gemm_kernel<<<(N_NODES + GEMM_TILE - 1) / GEMM_TILE, 512, GEMM_SMEM>>>(
        x, Wl, bl, Wr, br);
    edge_kernel<<<N_EDGES / 32, 256>>>(ei, att);
    finalize_kernel<<<N_NODES / 16, 256>>>(x, bias, gamma, beta, out);
}